// round 7
// baseline (speedup 1.0000x reference)
#include <cuda_runtime.h>

#define NB  4
#define NSQ 512
#define NSK 512
#define ND  512
#define NS  128

typedef unsigned long long ull;

// ---- packed f32x2 helpers ----
__device__ __forceinline__ void fma2(ull& d, ull a, ull b) {
    asm("fma.rn.f32x2 %0, %1, %2, %0;" : "+l"(d) : "l"(a), "l"(b));
}
__device__ __forceinline__ ull pack2(float x, float y) {
    ull r; asm("mov.b64 %0, {%1, %2};" : "=l"(r) : "f"(x), "f"(y)); return r;
}
__device__ __forceinline__ float2 unpack2(ull v) {
    float2 r; asm("mov.b64 {%0, %1}, %2;" : "=f"(r.x), "=f"(r.y) : "l"(v)); return r;
}

// ---- scratch (allocation-free) ----
__device__ __align__(16) float g_Wqh[ND * NS];
__device__ __align__(16) float g_Wkh[ND * NS];
__device__ __align__(16) float g_cA[NS];
__device__ __align__(16) float g_cK[NS];
__device__ __align__(16) float g_sg[NS];            // +-0.5 by sign of w2
__device__ __align__(16) float g_A2[NB * NSQ * NS]; // (q@Wqh + cA) * w2
__device__ __align__(16) float g_K2[NB * NSK * NS]; // (k@Wkh + cK) * w2
__device__ __align__(16) float g_CA[NB * NSQ];      // 0.5 * rowsum(A2)
__device__ __align__(16) float g_CK[NB * NSK];      // 0.5 * rowsum(K2)

// ---------------------------------------------------------------------------
// fold: Wqh = Wq @ W1[:S], Wkh = Wk @ W1[S:]  (+ bias/sg in block x==64)
// grid (65, 2), 128 threads
// ---------------------------------------------------------------------------
__global__ void fold_kernel(const float* __restrict__ Wq,
                            const float* __restrict__ Wk,
                            const float* __restrict__ W1,
                            const float* __restrict__ bq,
                            const float* __restrict__ bk,
                            const float* __restrict__ b1,
                            const float* __restrict__ W2) {
    int v = blockIdx.y, s = threadIdx.x;
    if (blockIdx.x == 64) {
        if (v == 0) {
            float a = b1[s];
#pragma unroll 8
            for (int t = 0; t < NS; t++) a = fmaf(bq[t], W1[t * NS + s], a);
            g_cA[s] = a;
            g_sg[s] = (W2[s] >= 0.f) ? 0.5f : -0.5f;
        } else {
            float c = 0.f;
#pragma unroll 8
            for (int t = 0; t < NS; t++) c = fmaf(bk[t], W1[(NS + t) * NS + s], c);
            g_cK[s] = c;
        }
        return;
    }
    int d0 = blockIdx.x * 8;
    __shared__ float wr[8][NS];
    const float* Wsrc = v ? Wk : Wq;
#pragma unroll
    for (int j = 0; j < 8; j++) wr[j][s] = Wsrc[(d0 + j) * NS + s];
    __syncthreads();
    const float* W1p = W1 + (v ? NS * NS : 0);
    float acc[8] = {};
#pragma unroll 8
    for (int t = 0; t < NS; t++) {
        float w = W1p[t * NS + s];
#pragma unroll
        for (int j = 0; j < 8; j++) acc[j] = fmaf(wr[j][t], w, acc[j]);
    }
    float* O = v ? g_Wkh : g_Wqh;
#pragma unroll
    for (int j = 0; j < 8; j++) O[(d0 + j) * NS + s] = acc[j];
}

// ---------------------------------------------------------------------------
// proj: A2 = (X @ Wfold + cb) * w2, plus CA = 0.5*rowsum(A2)
// BM=32, BN=128(full), BK=16. Warp owns 16 d cols; thread = 4q x 4d.
// ---------------------------------------------------------------------------
#define ASP 36
#define BSP 132

__global__ __launch_bounds__(256) void proj_kernel(const float* __restrict__ Xq,
                                                   const float* __restrict__ Xk,
                                                   const float* __restrict__ W2) {
    int v = blockIdx.y;
    const float* X    = v ? Xk : Xq;
    const float* Wf   = v ? g_Wkh : g_Wqh;
    const float* bias = v ? g_cK : g_cA;
    float* O          = v ? g_K2 : g_A2;
    float* CS         = v ? g_CK : g_CA;

    int m0  = blockIdx.x * 32;
    int tid = threadIdx.x;
    int w   = tid >> 5, lane = tid & 31;
    int qc  = lane >> 2, dc = lane & 3;

    __shared__ float As[16][ASP];     // X^T tile [k][q]
    __shared__ float Bs[16][BSP];     // W tile  [k][d]
    __shared__ float red[8][32];

    int r  = tid >> 3, c2 = (tid & 7) * 2;
    int rb = tid >> 4, cw = (tid & 15) * 8;

    float2 xv = *(const float2*)&X[(m0 + r) * ND + c2];
    float4 w0 = *(const float4*)&Wf[rb * NS + cw];
    float4 w1 = *(const float4*)&Wf[rb * NS + cw + 4];

    ull acc[4][2] = {};
    int db = w * 16 + dc * 4;

    for (int t = 0; t < ND / 16; t++) {
        As[c2][r] = xv.x; As[c2 + 1][r] = xv.y;
        *(float4*)&Bs[rb][cw]     = w0;
        *(float4*)&Bs[rb][cw + 4] = w1;
        __syncthreads();
        if (t + 1 < ND / 16) {
            int k0 = (t + 1) * 16;
            xv = *(const float2*)&X[(m0 + r) * ND + k0 + c2];
            w0 = *(const float4*)&Wf[(k0 + rb) * NS + cw];
            w1 = *(const float4*)&Wf[(k0 + rb) * NS + cw + 4];
        }
#pragma unroll
        for (int kk = 0; kk < 16; kk++) {
            float4 a = *(float4*)&As[kk][qc * 4];
            ulonglong2 bv = *(ulonglong2*)&Bs[kk][db];
            ull p0 = pack2(a.x, a.x), p1 = pack2(a.y, a.y);
            ull p2 = pack2(a.z, a.z), p3 = pack2(a.w, a.w);
            fma2(acc[0][0], p0, bv.x); fma2(acc[0][1], p0, bv.y);
            fma2(acc[1][0], p1, bv.x); fma2(acc[1][1], p1, bv.y);
            fma2(acc[2][0], p2, bv.x); fma2(acc[2][1], p2, bv.y);
            fma2(acc[3][0], p3, bv.x); fma2(acc[3][1], p3, bv.y);
        }
        __syncthreads();
    }

    float4 cbv = *(const float4*)&bias[db];
    float4 w2v = *(const float4*)&W2[db];
    float rsum[4];
#pragma unroll
    for (int j = 0; j < 4; j++) {
        int row = m0 + qc * 4 + j;
        float2 p0 = unpack2(acc[j][0]), p1 = unpack2(acc[j][1]);
        float4 o;
        o.x = (p0.x + cbv.x) * w2v.x; o.y = (p0.y + cbv.y) * w2v.y;
        o.z = (p1.x + cbv.z) * w2v.z; o.w = (p1.y + cbv.w) * w2v.w;
        *(float4*)&O[row * NS + db] = o;
        rsum[j] = o.x + o.y + o.z + o.w;
    }
#pragma unroll
    for (int j = 0; j < 4; j++) {
        rsum[j] += __shfl_xor_sync(0xffffffffu, rsum[j], 1);
        rsum[j] += __shfl_xor_sync(0xffffffffu, rsum[j], 2);
    }
    if (dc == 0) {
#pragma unroll
        for (int j = 0; j < 4; j++) red[w][qc * 4 + j] = rsum[j];
    }
    __syncthreads();
    if (tid < 32) {
        float s = 0.f;
#pragma unroll
        for (int ww = 0; ww < 8; ww++) s += red[ww][tid];
        CS[m0 + tid] = 0.5f * s;
    }
}

// ---------------------------------------------------------------------------
// scores + softmax + attn write (unchanged; measured 30.9us)
// ---------------------------------------------------------------------------
#define TQ  8
#define KMP 132
#define SCP 516

__global__ __launch_bounds__(256) void score_kernel(const int* __restrict__ mask,
                                                    const float* __restrict__ b2,
                                                    float* __restrict__ attn_out) {
    extern __shared__ float sm[];
    float* qcs = sm;                    // TQ*NS   = 1024 f
    float* sgs = qcs + TQ * NS;         // 128 f
    float* cks = sgs + NS;              // 512 f
    float* cas = cks + NSK;             // 16 f
    float* kms = cas + 16;              // 128*132 = 16896 f
    float* scT = kms + 128 * KMP;       // TQ*516  = 4128 f

    int bx = blockIdx.x;
    int b  = bx >> 6;
    int q0 = (bx & 63) * TQ;
    int tid = threadIdx.x;

    {
        const float4* A4 = (const float4*)&g_A2[(b * NSQ + q0) * NS];
        ((float4*)qcs)[tid] = A4[tid];
        if (tid < 32)  ((float4*)sgs)[tid] = ((const float4*)g_sg)[tid];
        if (tid < 128) ((float4*)cks)[tid] = ((const float4*)(g_CK + b * NSK))[tid];
        if (tid < TQ)  cas[tid] = g_CA[b * NSQ + q0 + tid] + b2[0];
    }

    int kk = tid & 127;
    int qh = (tid >> 7) * 4;
    const float* qp = qcs + qh * NS;

    for (int k0 = 0; k0 < NSK; k0 += 128) {
        __syncthreads();
        const float4* K4 = (const float4*)&g_K2[(b * NSK + k0) * NS];
        for (int i = tid; i < 128 * 32; i += 256) {
            int kr = i >> 5, s4 = i & 31;
            *(float4*)&kms[kr * KMP + s4 * 4] = K4[i];
        }
        __syncthreads();

        float acc0 = 0.f, acc1 = 0.f, acc2 = 0.f, acc3 = 0.f;
#pragma unroll 8
        for (int s = 0; s < NS; s += 4) {
            float4 kv = *(float4*)&kms[kk * KMP + s];
            float4 sg = *(float4*)&sgs[s];
            float4 v0 = *(float4*)&qp[s];
            float4 v1 = *(float4*)&qp[NS + s];
            float4 v2 = *(float4*)&qp[2 * NS + s];
            float4 v3 = *(float4*)&qp[3 * NS + s];
            acc0 = fmaf(sg.x, fabsf(v0.x + kv.x), acc0);
            acc0 = fmaf(sg.y, fabsf(v0.y + kv.y), acc0);
            acc0 = fmaf(sg.z, fabsf(v0.z + kv.z), acc0);
            acc0 = fmaf(sg.w, fabsf(v0.w + kv.w), acc0);
            acc1 = fmaf(sg.x, fabsf(v1.x + kv.x), acc1);
            acc1 = fmaf(sg.y, fabsf(v1.y + kv.y), acc1);
            acc1 = fmaf(sg.z, fabsf(v1.z + kv.z), acc1);
            acc1 = fmaf(sg.w, fabsf(v1.w + kv.w), acc1);
            acc2 = fmaf(sg.x, fabsf(v2.x + kv.x), acc2);
            acc2 = fmaf(sg.y, fabsf(v2.y + kv.y), acc2);
            acc2 = fmaf(sg.z, fabsf(v2.z + kv.z), acc2);
            acc2 = fmaf(sg.w, fabsf(v2.w + kv.w), acc2);
            acc3 = fmaf(sg.x, fabsf(v3.x + kv.x), acc3);
            acc3 = fmaf(sg.y, fabsf(v3.y + kv.y), acc3);
            acc3 = fmaf(sg.z, fabsf(v3.z + kv.z), acc3);
            acc3 = fmaf(sg.w, fabsf(v3.w + kv.w), acc3);
        }

        int kg = k0 + kk;
        float ckv = cks[kg];
        const int* mrow = mask + (b * NSQ + q0 + qh) * NSK + kg;
        float sc[4] = {acc0, acc1, acc2, acc3};
#pragma unroll
        for (int j = 0; j < 4; j++) {
            float s = sc[j] + cas[qh + j] + ckv;
            if (mrow[j * NSK] == 0) s = -1e9f;
            scT[(qh + j) * SCP + kg] = s;
        }
    }
    __syncthreads();

    {
        int q = tid >> 5, lane = tid & 31;
        float4 v[4];
        float mx = -3.0e38f;
#pragma unroll
        for (int j = 0; j < 4; j++) {
            v[j] = *(float4*)&scT[q * SCP + j * 128 + lane * 4];
            mx = fmaxf(mx, fmaxf(fmaxf(v[j].x, v[j].y), fmaxf(v[j].z, v[j].w)));
        }
#pragma unroll
        for (int o = 16; o; o >>= 1) mx = fmaxf(mx, __shfl_xor_sync(0xffffffffu, mx, o));
        float sum = 0.f;
#pragma unroll
        for (int j = 0; j < 4; j++) {
            v[j].x = __expf(v[j].x - mx); v[j].y = __expf(v[j].y - mx);
            v[j].z = __expf(v[j].z - mx); v[j].w = __expf(v[j].w - mx);
            sum += v[j].x + v[j].y + v[j].z + v[j].w;
        }
#pragma unroll
        for (int o = 16; o; o >>= 1) sum += __shfl_xor_sync(0xffffffffu, sum, o);
        float inv = 1.0f / sum;
        float* arow = attn_out + (b * NSQ + q0 + q) * NSK;
#pragma unroll
        for (int j = 0; j < 4; j++) {
            float4 wv;
            wv.x = v[j].x * inv; wv.y = v[j].y * inv;
            wv.z = v[j].z * inv; wv.w = v[j].w * inv;
            *(float4*)&arow[j * 128 + lane * 4] = wv;
        }
    }
}

// ---------------------------------------------------------------------------
// AV GEMM: out = attn @ V.  BM=32 q x BN=128 d x BK=16, 256 thr.
// Warp owns 16 d; thread = 4q x 4d. Double-buffered. grid (4,16,4)=256 blocks.
// ---------------------------------------------------------------------------
#define ATP 36
#define BVP 132

__global__ __launch_bounds__(256) void av_kernel(const float* __restrict__ attn,
                                                 const float* __restrict__ Vv,
                                                 float* __restrict__ out) {
    int b  = blockIdx.z;
    int q0 = blockIdx.y * 32;
    int d0 = blockIdx.x * 128;
    int tid = threadIdx.x;
    int w = tid >> 5, lane = tid & 31;
    int qc = lane >> 2, dc = lane & 3;

    __shared__ float At[2][16][ATP];   // attn^T tile [k][q]
    __shared__ float Bs[2][16][BVP];   // V tile [k][d]

    const float* Ab = attn + (b * NSQ + q0) * NSK;
    const float* Vb = Vv + b * NSK * ND + d0;

    int ra = tid >> 3, ca = (tid & 7) * 2;     // attn: q=ra (0..31), k=ca,ca+1
    int rb = tid >> 5, cb = (tid & 31) * 4;    // V: k rows rb, rb+8

    float2 a  = *(const float2*)&Ab[ra * NSK + ca];
    float4 v0 = *(const float4*)&Vb[rb * ND + cb];
    float4 v1 = *(const float4*)&Vb[(rb + 8) * ND + cb];
    At[0][ca][ra] = a.x; At[0][ca + 1][ra] = a.y;
    *(float4*)&Bs[0][rb][cb] = v0;
    *(float4*)&Bs[0][rb + 8][cb] = v1;
    __syncthreads();

    ull acc[4][2] = {};
    int db = w * 16 + dc * 4;

    for (int t = 0; t < NSK / 16; t++) {
        int cur = t & 1;
        if (t + 1 < NSK / 16) {
            int k0 = (t + 1) * 16;
            a  = *(const float2*)&Ab[ra * NSK + k0 + ca];
            v0 = *(const float4*)&Vb[(k0 + rb) * ND + cb];
            v1 = *(const float4*)&Vb[(k0 + rb + 8) * ND + cb];
        }
#pragma unroll
        for (int kk = 0; kk < 16; kk++) {
            float4 av = *(float4*)&At[cur][kk][qc * 4];        // conflict-free
            ulonglong2 bv = *(ulonglong2*)&Bs[cur][kk][db];    // 4 distinct/warp
            ull p0 = pack2(av.x, av.x), p1 = pack2(av.y, av.y);
            ull p2 = pack2(av.z, av.z), p3 = pack2(av.w, av.w);
            fma2(acc[0][0], p0, bv.x); fma2(acc[0][1], p0, bv.y);
            fma2(acc[1][0], p1, bv.x); fma2(acc[1][1], p1, bv.y);
            fma2(acc[2][0], p2, bv.x); fma2(acc[2][1], p2, bv.y);
            fma2(acc[3][0], p3, bv.x); fma2(acc[3][1], p3, bv.y);
        }
        if (t + 1 < NSK / 16) {
            int nxt = cur ^ 1;
            At[nxt][ca][ra] = a.x; At[nxt][ca + 1][ra] = a.y;
            *(float4*)&Bs[nxt][rb][cb] = v0;
            *(float4*)&Bs[nxt][rb + 8][cb] = v1;
        }
        __syncthreads();
    }

    float* Ob = out + (b * NSQ + q0 + qc * 4) * ND + d0 + db;
#pragma unroll
    for (int j = 0; j < 4; j++) {
        ulonglong2 s;
        s.x = acc[j][0]; s.y = acc[j][1];
        *(ulonglong2*)&Ob[j * ND] = s;
    }
}

// ---------------------------------------------------------------------------
#define SMEM_SC ((TQ * NS + NS + NSK + 16 + 128 * KMP + TQ * SCP) * 4)

extern "C" void kernel_launch(void* const* d_in, const int* in_sizes, int n_in,
                              void* d_out, int out_size) {
    const float* query = (const float*)d_in[0];
    const float* key   = (const float*)d_in[1];
    const float* value = (const float*)d_in[2];
    const int*   mask  = (const int*)d_in[3];
    const float* Wq = (const float*)d_in[4];
    const float* bq = (const float*)d_in[5];
    const float* Wk = (const float*)d_in[6];
    const float* bk = (const float*)d_in[7];
    const float* W1 = (const float*)d_in[8];
    const float* b1 = (const float*)d_in[9];
    const float* W2 = (const float*)d_in[10];
    const float* b2 = (const float*)d_in[11];

    float* out  = (float*)d_out;
    float* attn = out + NB * NSQ * ND;

    cudaFuncSetAttribute(score_kernel,
                         cudaFuncAttributeMaxDynamicSharedMemorySize, SMEM_SC);

    fold_kernel<<<dim3(65, 2), 128>>>(Wq, Wk, W1, bq, bk, b1, W2);
    proj_kernel<<<dim3(64, 2), 256>>>(query, key, W2);
    score_kernel<<<NB * NSQ / TQ, 256, SMEM_SC>>>(mask, b2, attn);
    av_kernel<<<dim3(4, 16, 4), 256>>>(attn, value, out);
}

// round 8
// speedup vs baseline: 1.1118x; 1.1118x over previous
#include <cuda_runtime.h>

#define NB  4
#define NSQ 512
#define NSK 512
#define ND  512
#define NS  128

typedef unsigned long long ull;

// ---- packed f32x2 helpers ----
__device__ __forceinline__ void fma2(ull& d, ull a, ull b) {
    asm("fma.rn.f32x2 %0, %1, %2, %0;" : "+l"(d) : "l"(a), "l"(b));
}
__device__ __forceinline__ ull add2(ull a, ull b) {
    ull r; asm("add.rn.f32x2 %0, %1, %2;" : "=l"(r) : "l"(a), "l"(b)); return r;
}
__device__ __forceinline__ ull pack2(float x, float y) {
    ull r; asm("mov.b64 %0, {%1, %2};" : "=l"(r) : "f"(x), "f"(y)); return r;
}
__device__ __forceinline__ float2 unpack2(ull v) {
    float2 r; asm("mov.b64 {%0, %1}, %2;" : "=f"(r.x), "=f"(r.y) : "l"(v)); return r;
}

#define SMASK 0x7fffffff7fffffffULL

// ---- scratch (allocation-free) ----
__device__ __align__(16) float g_Wqh[ND * NS];
__device__ __align__(16) float g_Wkh[ND * NS];
__device__ __align__(16) float g_cA[NS];
__device__ __align__(16) float g_cK[NS];
__device__ __align__(16) float g_sg[NS];            // +-0.5 by sign of w2
__device__ __align__(16) float g_A2[NB * NSQ * NS]; // (q@Wqh + cA) * w2
__device__ __align__(16) float g_K2[NB * NSK * NS]; // (k@Wkh + cK) * w2
__device__ __align__(16) float g_CA[NB * NSQ];      // 0.5 * rowsum(A2)
__device__ __align__(16) float g_CK[NB * NSK];      // 0.5 * rowsum(K2)

// ---------------------------------------------------------------------------
// fold: Wqh = Wq @ W1[:S], Wkh = Wk @ W1[S:]  (+ bias/sg in block x==64)
// ---------------------------------------------------------------------------
__global__ void fold_kernel(const float* __restrict__ Wq,
                            const float* __restrict__ Wk,
                            const float* __restrict__ W1,
                            const float* __restrict__ bq,
                            const float* __restrict__ bk,
                            const float* __restrict__ b1,
                            const float* __restrict__ W2) {
    int v = blockIdx.y, s = threadIdx.x;
    if (blockIdx.x == 64) {
        if (v == 0) {
            float a = b1[s];
#pragma unroll 8
            for (int t = 0; t < NS; t++) a = fmaf(bq[t], W1[t * NS + s], a);
            g_cA[s] = a;
            g_sg[s] = (W2[s] >= 0.f) ? 0.5f : -0.5f;
        } else {
            float c = 0.f;
#pragma unroll 8
            for (int t = 0; t < NS; t++) c = fmaf(bk[t], W1[(NS + t) * NS + s], c);
            g_cK[s] = c;
        }
        return;
    }
    int d0 = blockIdx.x * 8;
    __shared__ float wr[8][NS];
    const float* Wsrc = v ? Wk : Wq;
#pragma unroll
    for (int j = 0; j < 8; j++) wr[j][s] = Wsrc[(d0 + j) * NS + s];
    __syncthreads();
    const float* W1p = W1 + (v ? NS * NS : 0);
    float acc[8] = {};
#pragma unroll 8
    for (int t = 0; t < NS; t++) {
        float w = W1p[t * NS + s];
#pragma unroll
        for (int j = 0; j < 8; j++) acc[j] = fmaf(wr[j][t], w, acc[j]);
    }
    float* O = v ? g_Wkh : g_Wqh;
#pragma unroll
    for (int j = 0; j < 8; j++) O[(d0 + j) * NS + s] = acc[j];
}

// ---------------------------------------------------------------------------
// proj: A2 = (X @ Wfold + cb) * w2, plus CA = 0.5*rowsum(A2)
// BM=32, BN=128(full), BK=16. Warp owns 16 d cols; thread = 4q x 4d.
// ---------------------------------------------------------------------------
#define ASP 36
#define BSP 132

__global__ __launch_bounds__(256) void proj_kernel(const float* __restrict__ Xq,
                                                   const float* __restrict__ Xk,
                                                   const float* __restrict__ W2) {
    int v = blockIdx.y;
    const float* X    = v ? Xk : Xq;
    const float* Wf   = v ? g_Wkh : g_Wqh;
    const float* bias = v ? g_cK : g_cA;
    float* O          = v ? g_K2 : g_A2;
    float* CS         = v ? g_CK : g_CA;

    int m0  = blockIdx.x * 32;
    int tid = threadIdx.x;
    int w   = tid >> 5, lane = tid & 31;
    int qc  = lane >> 2, dc = lane & 3;

    __shared__ float As[16][ASP];     // X^T tile [k][q]
    __shared__ float Bs[16][BSP];     // W tile  [k][d]
    __shared__ float red[8][32];

    int r  = tid >> 3, c2 = (tid & 7) * 2;
    int rb = tid >> 4, cw = (tid & 15) * 8;

    float2 xv = *(const float2*)&X[(m0 + r) * ND + c2];
    float4 w0 = *(const float4*)&Wf[rb * NS + cw];
    float4 w1 = *(const float4*)&Wf[rb * NS + cw + 4];

    ull acc[4][2] = {};
    int db = w * 16 + dc * 4;

    for (int t = 0; t < ND / 16; t++) {
        As[c2][r] = xv.x; As[c2 + 1][r] = xv.y;
        *(float4*)&Bs[rb][cw]     = w0;
        *(float4*)&Bs[rb][cw + 4] = w1;
        __syncthreads();
        if (t + 1 < ND / 16) {
            int k0 = (t + 1) * 16;
            xv = *(const float2*)&X[(m0 + r) * ND + k0 + c2];
            w0 = *(const float4*)&Wf[(k0 + rb) * NS + cw];
            w1 = *(const float4*)&Wf[(k0 + rb) * NS + cw + 4];
        }
#pragma unroll
        for (int kk = 0; kk < 16; kk++) {
            float4 a = *(float4*)&As[kk][qc * 4];
            ulonglong2 bv = *(ulonglong2*)&Bs[kk][db];
            ull p0 = pack2(a.x, a.x), p1 = pack2(a.y, a.y);
            ull p2 = pack2(a.z, a.z), p3 = pack2(a.w, a.w);
            fma2(acc[0][0], p0, bv.x); fma2(acc[0][1], p0, bv.y);
            fma2(acc[1][0], p1, bv.x); fma2(acc[1][1], p1, bv.y);
            fma2(acc[2][0], p2, bv.x); fma2(acc[2][1], p2, bv.y);
            fma2(acc[3][0], p3, bv.x); fma2(acc[3][1], p3, bv.y);
        }
        __syncthreads();
    }

    float4 cbv = *(const float4*)&bias[db];
    float4 w2v = *(const float4*)&W2[db];
    float rsum[4];
#pragma unroll
    for (int j = 0; j < 4; j++) {
        int row = m0 + qc * 4 + j;
        float2 p0 = unpack2(acc[j][0]), p1 = unpack2(acc[j][1]);
        float4 o;
        o.x = (p0.x + cbv.x) * w2v.x; o.y = (p0.y + cbv.y) * w2v.y;
        o.z = (p1.x + cbv.z) * w2v.z; o.w = (p1.y + cbv.w) * w2v.w;
        *(float4*)&O[row * NS + db] = o;
        rsum[j] = o.x + o.y + o.z + o.w;
    }
#pragma unroll
    for (int j = 0; j < 4; j++) {
        rsum[j] += __shfl_xor_sync(0xffffffffu, rsum[j], 1);
        rsum[j] += __shfl_xor_sync(0xffffffffu, rsum[j], 2);
    }
    if (dc == 0) {
#pragma unroll
        for (int j = 0; j < 4; j++) red[w][qc * 4 + j] = rsum[j];
    }
    __syncthreads();
    if (tid < 32) {
        float s = 0.f;
#pragma unroll
        for (int ww = 0; ww < 8; ww++) s += red[ww][tid];
        CS[m0 + tid] = 0.5f * s;
    }
}

// ---------------------------------------------------------------------------
// scores + softmax + attn write.  128 threads, thread = 1 k x 8 q.
// Inner loop: add.f32x2 (fma pipe) + AND-abs (alu pipe) + fma.f32x2 (fma pipe)
// grid NB*NSQ/8 = 256 blocks, ~91KB smem -> 2 CTA/SM
// ---------------------------------------------------------------------------
#define TQ  8
#define KMP 132
#define SCP 516

__global__ __launch_bounds__(128) void score_kernel(const int* __restrict__ mask,
                                                    const float* __restrict__ b2,
                                                    float* __restrict__ attn_out) {
    extern __shared__ float sm[];
    float* qcs = sm;                    // TQ*NS   = 1024 f
    float* sgs = qcs + TQ * NS;         // 128 f
    float* cks = sgs + NS;              // 512 f
    float* cas = cks + NSK;             // 16 f
    float* kms = cas + 16;              // 128*132 = 16896 f
    float* scT = kms + 128 * KMP;       // TQ*516  = 4128 f

    int bx = blockIdx.x;
    int b  = bx >> 6;
    int q0 = (bx & 63) * TQ;
    int tid = threadIdx.x;              // 0..127 == kk

    {
        const float4* A4 = (const float4*)&g_A2[(b * NSQ + q0) * NS];
        ((float4*)qcs)[tid]       = A4[tid];
        ((float4*)qcs)[tid + 128] = A4[tid + 128];
        if (tid < 32) ((float4*)sgs)[tid] = ((const float4*)g_sg)[tid];
        ((float4*)cks)[tid] = ((const float4*)(g_CK + b * NSK))[tid];
        if (tid < TQ) cas[tid] = g_CA[b * NSQ + q0 + tid] + b2[0];
    }

    for (int k0 = 0; k0 < NSK; k0 += 128) {
        __syncthreads();
        const float4* K4 = (const float4*)&g_K2[(b * NSK + k0) * NS];
#pragma unroll
        for (int i = 0; i < 32; i++) {
            int idx = i * 128 + tid;
            int kr = idx >> 5, s4 = idx & 31;
            *(float4*)&kms[kr * KMP + s4 * 4] = K4[idx];
        }
        __syncthreads();

        ull acc[TQ] = {};
#pragma unroll 8
        for (int s = 0; s < NS; s += 4) {
            ulonglong2 kv = *(ulonglong2*)&kms[tid * KMP + s];   // conflict-free
            ulonglong2 sg = *(ulonglong2*)&sgs[s];               // broadcast
#pragma unroll
            for (int q = 0; q < TQ; q++) {
                ulonglong2 qv = *(ulonglong2*)&qcs[q * NS + s];  // broadcast
                ull x0 = add2(qv.x, kv.x) & SMASK;               // alu abs
                ull x1 = add2(qv.y, kv.y) & SMASK;
                fma2(acc[q], sg.x, x0);
                fma2(acc[q], sg.y, x1);
            }
        }

        int kg = k0 + tid;
        float ckv = cks[kg];
        const int* mrow = mask + (b * NSQ + q0) * NSK + kg;
#pragma unroll
        for (int q = 0; q < TQ; q++) {
            float2 p = unpack2(acc[q]);
            float s = p.x + p.y + cas[q] + ckv;
            if (mrow[q * NSK] == 0) s = -1e9f;
            scT[q * SCP + kg] = s;
        }
    }
    __syncthreads();

    // softmax: warp w handles q = 2w, 2w+1; write normalized attn to gmem
    {
        int w = tid >> 5, lane = tid & 31;
#pragma unroll
        for (int qq = 0; qq < 2; qq++) {
            int q = w * 2 + qq;
            float4 v[4];
            float mx = -3.0e38f;
#pragma unroll
            for (int j = 0; j < 4; j++) {
                v[j] = *(float4*)&scT[q * SCP + j * 128 + lane * 4];
                mx = fmaxf(mx, fmaxf(fmaxf(v[j].x, v[j].y), fmaxf(v[j].z, v[j].w)));
            }
#pragma unroll
            for (int o = 16; o; o >>= 1) mx = fmaxf(mx, __shfl_xor_sync(0xffffffffu, mx, o));
            float sum = 0.f;
#pragma unroll
            for (int j = 0; j < 4; j++) {
                v[j].x = __expf(v[j].x - mx); v[j].y = __expf(v[j].y - mx);
                v[j].z = __expf(v[j].z - mx); v[j].w = __expf(v[j].w - mx);
                sum += v[j].x + v[j].y + v[j].z + v[j].w;
            }
#pragma unroll
            for (int o = 16; o; o >>= 1) sum += __shfl_xor_sync(0xffffffffu, sum, o);
            float inv = 1.0f / sum;
            float* arow = attn_out + (b * NSQ + q0 + q) * NSK;
#pragma unroll
            for (int j = 0; j < 4; j++) {
                float4 wv;
                wv.x = v[j].x * inv; wv.y = v[j].y * inv;
                wv.z = v[j].z * inv; wv.w = v[j].w * inv;
                *(float4*)&arow[j * 128 + lane * 4] = wv;
            }
        }
    }
}

// ---------------------------------------------------------------------------
// AV GEMM (R6 version, part of the measured-90.6 run): BM=64 x BN=128 x BK=16,
// 256 thr, warp owns 16 d, thread = 8q x 4d, double-buffered. grid (4,8,4).
// ---------------------------------------------------------------------------
#define ATP 68
#define BVP 132

__global__ __launch_bounds__(256) void av_kernel(const float* __restrict__ attn,
                                                 const float* __restrict__ Vv,
                                                 float* __restrict__ out) {
    int b  = blockIdx.z;
    int q0 = blockIdx.y * 64;
    int d0 = blockIdx.x * 128;
    int tid = threadIdx.x;
    int w = tid >> 5, lane = tid & 31;
    int qc = lane >> 2, dc = lane & 3;

    __shared__ float At[2][16][ATP];   // attn^T tile [k][q]
    __shared__ float Bs[2][16][BVP];   // V tile [k][d]

    const float* Ab = attn + (b * NSQ + q0) * NSK;
    const float* Vb = Vv + b * NSK * ND + d0;

    int ra = tid >> 2, ca = (tid & 3) * 4;        // attn: q=ra, k=ca..ca+3
    int rb0 = tid >> 5, cb0 = (tid & 31) * 4;     // V: k rows rb0, rb0+8

    float4 a  = *(const float4*)&Ab[ra * NSK + ca];
    float4 v0 = *(const float4*)&Vb[rb0 * ND + cb0];
    float4 v1 = *(const float4*)&Vb[(rb0 + 8) * ND + cb0];
    At[0][ca][ra] = a.x; At[0][ca + 1][ra] = a.y;
    At[0][ca + 2][ra] = a.z; At[0][ca + 3][ra] = a.w;
    *(float4*)&Bs[0][rb0][cb0] = v0;
    *(float4*)&Bs[0][rb0 + 8][cb0] = v1;
    __syncthreads();

    ull acc[8][2] = {};
    int db = w * 16 + dc * 4;

    for (int t = 0; t < NSK / 16; t++) {
        int cur = t & 1;
        if (t + 1 < NSK / 16) {
            int k0 = (t + 1) * 16;
            a  = *(const float4*)&Ab[ra * NSK + k0 + ca];
            v0 = *(const float4*)&Vb[(k0 + rb0) * ND + cb0];
            v1 = *(const float4*)&Vb[(k0 + rb0 + 8) * ND + cb0];
        }
#pragma unroll
        for (int kk = 0; kk < 16; kk++) {
            float4 a0 = *(float4*)&At[cur][kk][qc * 8];
            float4 a1 = *(float4*)&At[cur][kk][qc * 8 + 4];
            ulonglong2 bv = *(ulonglong2*)&Bs[cur][kk][db];
            ull p0 = pack2(a0.x, a0.x), p1 = pack2(a0.y, a0.y);
            ull p2 = pack2(a0.z, a0.z), p3 = pack2(a0.w, a0.w);
            fma2(acc[0][0], p0, bv.x); fma2(acc[0][1], p0, bv.y);
            fma2(acc[1][0], p1, bv.x); fma2(acc[1][1], p1, bv.y);
            fma2(acc[2][0], p2, bv.x); fma2(acc[2][1], p2, bv.y);
            fma2(acc[3][0], p3, bv.x); fma2(acc[3][1], p3, bv.y);
            ull p4 = pack2(a1.x, a1.x), p5 = pack2(a1.y, a1.y);
            ull p6 = pack2(a1.z, a1.z), p7 = pack2(a1.w, a1.w);
            fma2(acc[4][0], p4, bv.x); fma2(acc[4][1], p4, bv.y);
            fma2(acc[5][0], p5, bv.x); fma2(acc[5][1], p5, bv.y);
            fma2(acc[6][0], p6, bv.x); fma2(acc[6][1], p6, bv.y);
            fma2(acc[7][0], p7, bv.x); fma2(acc[7][1], p7, bv.y);
        }
        if (t + 1 < NSK / 16) {
            int nxt = cur ^ 1;
            At[nxt][ca][ra] = a.x; At[nxt][ca + 1][ra] = a.y;
            At[nxt][ca + 2][ra] = a.z; At[nxt][ca + 3][ra] = a.w;
            *(float4*)&Bs[nxt][rb0][cb0] = v0;
            *(float4*)&Bs[nxt][rb0 + 8][cb0] = v1;
        }
        __syncthreads();
    }

    float* Ob = out + (b * NSQ + q0 + qc * 8) * ND + d0 + db;
#pragma unroll
    for (int j = 0; j < 8; j++) {
        ulonglong2 s;
        s.x = acc[j][0]; s.y = acc[j][1];
        *(ulonglong2*)&Ob[j * ND] = s;
    }
}

// ---------------------------------------------------------------------------
#define SMEM_SC ((TQ * NS + NS + NSK + 16 + 128 * KMP + TQ * SCP) * 4)

extern "C" void kernel_launch(void* const* d_in, const int* in_sizes, int n_in,
                              void* d_out, int out_size) {
    const float* query = (const float*)d_in[0];
    const float* key   = (const float*)d_in[1];
    const float* value = (const float*)d_in[2];
    const int*   mask  = (const int*)d_in[3];
    const float* Wq = (const float*)d_in[4];
    const float* bq = (const float*)d_in[5];
    const float* Wk = (const float*)d_in[6];
    const float* bk = (const float*)d_in[7];
    const float* W1 = (const float*)d_in[8];
    const float* b1 = (const float*)d_in[9];
    const float* W2 = (const float*)d_in[10];
    const float* b2 = (const float*)d_in[11];

    float* out  = (float*)d_out;
    float* attn = out + NB * NSQ * ND;

    cudaFuncSetAttribute(score_kernel,
                         cudaFuncAttributeMaxDynamicSharedMemorySize, SMEM_SC);

    fold_kernel<<<dim3(65, 2), 128>>>(Wq, Wk, W1, bq, bk, b1, W2);
    proj_kernel<<<dim3(64, 2), 256>>>(query, key, W2);
    score_kernel<<<NB * NSQ / TQ, 128, SMEM_SC>>>(mask, b2, attn);
    av_kernel<<<dim3(4, 8, 4), 256>>>(attn, value, out);
}